// round 9
// baseline (speedup 1.0000x reference)
#include <cuda_runtime.h>
#include <cuda_bf16.h>
#include <math.h>

#define NMAX   100000
#define EMAX   1600000
#define FH     64

// Scratch (alloc-free rule: __device__ globals)
__device__ float g_A[NMAX * FH];      // gather source h'
__device__ float g_B[NMAX * FH];      // aggregation output
__device__ float g_dinv[NMAX];
__device__ int2  g_edges[EMAX];       // packed (src,dst)
__device__ int   g_cnt[NMAX];         // in-degree (excl self-loop)
__device__ int   g_off[NMAX + 1];     // CSR offsets
__device__ int   g_fill[NMAX];        // fill cursors
__device__ int   g_src[EMAX];         // CSR src indices (grouped by dst)
__device__ int   g_is64;

// ---------------------------------------------------------------------------
// Detect int64 vs int32 edge_index (values < 100000 -> all int64 high words 0)
__global__ void probe_dtype(const long long* __restrict__ ei) {
    __shared__ int any;
    if (threadIdx.x == 0) any = 0;
    __syncthreads();
    for (int i = threadIdx.x; i < 1024; i += blockDim.x) {
        long long v = ei[i];
        if ((v >> 32) != 0) any = 1;
    }
    __syncthreads();
    if (threadIdx.x == 0) g_is64 = (any == 0) ? 1 : 0;
}

__global__ void init_cnt(int n) {
    int i = blockIdx.x * blockDim.x + threadIdx.x;
    if (i < n) g_cnt[i] = 0;
}

// Convert edges to packed int2 + count in-degree
__global__ void convert_cnt(const void* __restrict__ ei, int E) {
    int e = blockIdx.x * blockDim.x + threadIdx.x;
    if (e >= E) return;
    int s, d;
    if (g_is64) {
        const long long* p = (const long long*)ei;
        s = (int)p[e]; d = (int)p[E + e];
    } else {
        const int* p = (const int*)ei;
        s = p[e]; d = p[E + e];
    }
    g_edges[e] = make_int2(s, d);
    atomicAdd(&g_cnt[d], 1);
}

// Single-block exclusive scan of g_cnt -> g_off (and g_fill copy).
__global__ void scan_kernel(int n) {
    __shared__ int sums[1024];
    int t = threadIdx.x;
    int chunk = (n + 1023) >> 10;
    int lo = t * chunk;
    int hi = min(lo + chunk, n);
    int s = 0;
    #pragma unroll 4
    for (int i = lo; i < hi; i++) s += g_cnt[i];
    sums[t] = s;
    __syncthreads();
    // Hillis-Steele inclusive scan
    for (int off = 1; off < 1024; off <<= 1) {
        int tmp = (t >= off) ? sums[t - off] : 0;
        __syncthreads();
        sums[t] += tmp;
        __syncthreads();
    }
    int run = (t == 0) ? 0 : sums[t - 1];
    #pragma unroll 4
    for (int i = lo; i < hi; i++) {
        g_off[i] = run;
        g_fill[i] = run;
        run += g_cnt[i];
    }
    if (lo < n && hi == n) g_off[n] = run;
}

__global__ void dinv_kernel(int n) {
    int i = blockIdx.x * blockDim.x + threadIdx.x;
    if (i < n) g_dinv[i] = rsqrtf((float)(g_cnt[i] + 1));   // +1 self-loop
}

// Fill CSR: g_src grouped by dst
__global__ void fill_kernel(int E) {
    int e = blockIdx.x * blockDim.x + threadIdx.x;
    if (e >= E) return;
    int2 ed = g_edges[e];
    int pos = atomicAdd(&g_fill[ed.y], 1);
    g_src[pos] = ed.x;
}

// ---------------------------------------------------------------------------
// Atomic-free aggregation: B[d,:] = A[d,:] + sum_{s in CSR[d]} A[s,:]
// One warp per node; lane owns a float2 (32*8B = 256B row).
__global__ void aggregate_kernel(const float* __restrict__ A, float* __restrict__ B, int n) {
    int warp = (blockIdx.x * blockDim.x + threadIdx.x) >> 5;
    int lane = threadIdx.x & 31;
    if (warp >= n) return;
    int beg = g_off[warp];
    int end = g_off[warp + 1];
    const float2* Ab = (const float2*)A;
    float2 acc = Ab[(size_t)warp * 32 + lane];   // self-loop term
    int i = beg;
    for (; i + 4 <= end; i += 4) {
        int s0 = g_src[i], s1 = g_src[i + 1], s2 = g_src[i + 2], s3 = g_src[i + 3];
        float2 v0 = Ab[(size_t)s0 * 32 + lane];
        float2 v1 = Ab[(size_t)s1 * 32 + lane];
        float2 v2 = Ab[(size_t)s2 * 32 + lane];
        float2 v3 = Ab[(size_t)s3 * 32 + lane];
        acc.x += (v0.x + v1.x) + (v2.x + v3.x);
        acc.y += (v0.y + v1.y) + (v2.y + v3.y);
    }
    for (; i < end; i++) {
        int s = g_src[i];
        float2 v = Ab[(size_t)s * 32 + lane];
        acc.x += v.x;
        acc.y += v.y;
    }
    ((float2*)B)[(size_t)warp * 32 + lane] = acc;
}

// ---------------------------------------------------------------------------
// Tiled fp32 GEMM: out = f(X) @ W, 64-row tiles, 4x4 thread tile.
// TRANS: x_load = relu(dinv[row]*x + bin[col])
// FC==0: epilogue v *= dinv[row], write O1 (gather source A)
// FC==1: epilogue v += bout[col], write O1
template<int K, int N, bool TRANS, bool FC>
__global__ void gemm_kernel(const float* X, const float* __restrict__ W,
                            const float* __restrict__ bin, const float* __restrict__ bout,
                            float* __restrict__ O1, int n) {
    constexpr int TX = N / 4;
    constexpr int NT = TX * 16;
    __shared__ float Xs[64][65];
    __shared__ float Ws[64][N];
    int row0 = blockIdx.x * 64;
    int tx = threadIdx.x, ty = threadIdx.y;
    int tid = ty * TX + tx;
    float acc[4][4] = {};

    for (int k0 = 0; k0 < K; k0 += 64) {
        for (int i = tid; i < 64 * 16; i += NT) {
            int r = i >> 4, c4 = i & 15;
            float4 v = make_float4(0.f, 0.f, 0.f, 0.f);
            int row = row0 + r;
            if (row < n) {
                v = *(const float4*)(X + (size_t)row * K + k0 + c4 * 4);
                if (TRANS) {
                    float s = g_dinv[row];
                    v.x = fmaxf(fmaf(v.x, s, bin[k0 + c4*4 + 0]), 0.f);
                    v.y = fmaxf(fmaf(v.y, s, bin[k0 + c4*4 + 1]), 0.f);
                    v.z = fmaxf(fmaf(v.z, s, bin[k0 + c4*4 + 2]), 0.f);
                    v.w = fmaxf(fmaf(v.w, s, bin[k0 + c4*4 + 3]), 0.f);
                }
            }
            Xs[r][c4 * 4 + 0] = v.x; Xs[r][c4 * 4 + 1] = v.y;
            Xs[r][c4 * 4 + 2] = v.z; Xs[r][c4 * 4 + 3] = v.w;
        }
        for (int i = tid; i < 64 * (N / 4); i += NT) {
            int r = i / (N / 4), c4 = i % (N / 4);
            float4 v = *(const float4*)(W + (size_t)(k0 + r) * N + c4 * 4);
            *(float4*)&Ws[r][c4 * 4] = v;
        }
        __syncthreads();
        #pragma unroll
        for (int k = 0; k < 64; k++) {
            float4 w = *(float4*)&Ws[k][tx * 4];
            #pragma unroll
            for (int i = 0; i < 4; i++) {
                float a = Xs[ty * 4 + i][k];
                acc[i][0] += a * w.x;
                acc[i][1] += a * w.y;
                acc[i][2] += a * w.z;
                acc[i][3] += a * w.w;
            }
        }
        __syncthreads();
    }

    #pragma unroll
    for (int i = 0; i < 4; i++) {
        int row = row0 + ty * 4 + i;
        if (row >= n) continue;
        float4 o;
        if (FC) {
            o.x = acc[i][0] + bout[tx*4 + 0];
            o.y = acc[i][1] + bout[tx*4 + 1];
            o.z = acc[i][2] + bout[tx*4 + 2];
            o.w = acc[i][3] + bout[tx*4 + 3];
        } else {
            float s = g_dinv[row];
            o.x = acc[i][0] * s;
            o.y = acc[i][1] * s;
            o.z = acc[i][2] * s;
            o.w = acc[i][3] * s;
        }
        *(float4*)(O1 + (size_t)row * N + tx * 4) = o;
    }
}

// ---------------------------------------------------------------------------
extern "C" void kernel_launch(void* const* d_in, const int* in_sizes, int n_in,
                              void* d_out, int out_size) {
    const float* x   = (const float*)d_in[0];
    const void*  ei  = d_in[1];
    const float* W1  = (const float*)d_in[3];
    const float* b1  = (const float*)d_in[4];
    const float* W2  = (const float*)d_in[5];
    const float* b2  = (const float*)d_in[6];
    const float* Wfc = (const float*)d_in[7];
    const float* bfc = (const float*)d_in[8];
    float* out = (float*)d_out;

    int n = in_sizes[0] / 128;   // 100000
    int E = in_sizes[1] / 2;     // 1600000

    float *A, *B;
    cudaGetSymbolAddress((void**)&A, g_A);
    cudaGetSymbolAddress((void**)&B, g_B);

    int nb_n  = (n + 255) / 256;
    int nb_E  = (E + 255) / 256;
    int nb_ag = (n * 32 + 255) / 256;   // warp per node
    int nb_g  = (n + 63) / 64;

    // Prep: dtype probe, counts, scan -> CSR offsets, dinv, CSR fill
    probe_dtype<<<1, 256>>>((const long long*)ei);
    init_cnt<<<nb_n, 256>>>(n);
    convert_cnt<<<nb_E, 256>>>(ei, E);
    scan_kernel<<<1, 1024>>>(n);
    dinv_kernel<<<nb_n, 256>>>(n);
    fill_kernel<<<nb_E, 256>>>(E);

    // Layer 1: A = dinv*(x@W1); B = aggregate(A)
    gemm_kernel<128, 64, false, false><<<nb_g, dim3(16, 16)>>>(x, W1, nullptr, nullptr, A, n);
    aggregate_kernel<<<nb_ag, 256>>>(A, B, n);

    // Layer 2: X2 = relu(dinv*B + b1) on load; A = dinv*(X2@W2); B = aggregate(A)
    gemm_kernel<64, 64, true, false><<<nb_g, dim3(16, 16)>>>(B, W2, b1, nullptr, A, n);
    aggregate_kernel<<<nb_ag, 256>>>(A, B, n);

    // FC: out = relu(dinv*B + b2) @ Wfc + bfc
    gemm_kernel<64, 32, true, true><<<nb_g, dim3(8, 16)>>>(B, Wfc, b2, bfc, out, n);
}

// round 13
// speedup vs baseline: 1.7170x; 1.7170x over previous
#include <cuda_runtime.h>
#include <cuda_bf16.h>
#include <math.h>

#define NMAX   100000
#define EMAX   1600000
#define FH     64
#define SCAN_PER 1024                       // elems per scan block
#define SCAN_NB  ((NMAX + SCAN_PER - 1) / SCAN_PER)
#define CNT_PAD  (SCAN_NB * SCAN_PER)       // padded count-array size (int4-safe)

// Scratch (alloc-free rule: __device__ globals)
__device__ float g_A[NMAX * FH];      // gather source h'
__device__ float g_B[NMAX * FH];      // aggregation output
__device__ float g_dinv[NMAX];
__device__ int2  g_edges[EMAX];       // packed (src,dst)
__device__ int   g_cnt[CNT_PAD];      // in-degree (excl self-loop), padded
__device__ int   g_off[NMAX + 1];     // CSR offsets
__device__ int   g_fill[NMAX];        // fill cursors
__device__ int   g_src[EMAX];         // CSR src indices (grouped by dst)
__device__ int   g_bsum[256];         // scan block sums
__device__ int   g_is64;

// ---------------------------------------------------------------------------
// Detect int64 vs int32 edge_index (values < 100000 -> all int64 high words 0)
__global__ void probe_dtype(const long long* __restrict__ ei) {
    __shared__ int any;
    if (threadIdx.x == 0) any = 0;
    __syncthreads();
    for (int i = threadIdx.x; i < 1024; i += blockDim.x) {
        long long v = ei[i];
        if ((v >> 32) != 0) any = 1;
    }
    __syncthreads();
    if (threadIdx.x == 0) g_is64 = (any == 0) ? 1 : 0;
}

__global__ void init_cnt() {
    int i = blockIdx.x * blockDim.x + threadIdx.x;
    if (i < CNT_PAD) g_cnt[i] = 0;
}

// Convert edges to packed int2 + count in-degree
__global__ void convert_cnt(const void* __restrict__ ei, int E) {
    int e = blockIdx.x * blockDim.x + threadIdx.x;
    if (e >= E) return;
    int s, d;
    if (g_is64) {
        const long long* p = (const long long*)ei;
        s = (int)p[e]; d = (int)p[E + e];
    } else {
        const int* p = (const int*)ei;
        s = p[e]; d = p[E + e];
    }
    g_edges[e] = make_int2(s, d);
    atomicAdd(&g_cnt[d], 1);
}

// ---------------------------------------------------------------------------
// Multi-block exclusive scan of g_cnt[0..n) -> g_off (+ g_fill, g_off[n]).
// Phase 1: per-block sums (256 threads x 4 elems, int4 loads)
__global__ void scan_sums(int n) {
    __shared__ int red[256];
    int t = threadIdx.x;
    int i0 = blockIdx.x * SCAN_PER + t * 4;
    int4 v = *(const int4*)&g_cnt[i0];      // padded; counts beyond n are 0
    int s = v.x + v.y + v.z + v.w;
    red[t] = s;
    __syncthreads();
    #pragma unroll
    for (int off = 128; off > 0; off >>= 1) {
        if (t < off) red[t] += red[t + off];
        __syncthreads();
    }
    if (t == 0) g_bsum[blockIdx.x] = red[0];
}

// Phase 2: single block exclusive scan of block sums (nb <= 128)
__global__ void scan_tops(int nb) {
    __shared__ int sh[128];
    int t = threadIdx.x;
    int orig = (t < nb) ? g_bsum[t] : 0;
    sh[t] = orig;
    __syncthreads();
    #pragma unroll
    for (int off = 1; off < 128; off <<= 1) {
        int u = (t >= off) ? sh[t - off] : 0;
        __syncthreads();
        sh[t] += u;
        __syncthreads();
    }
    if (t < nb) g_bsum[t] = sh[t] - orig;   // exclusive
}

// Phase 3: local scan + write offsets/fill (thread owns 4 consecutive elems)
__global__ void scan_write(int n) {
    __shared__ int wsum[8];
    int t = threadIdx.x;
    int lane = t & 31, wid = t >> 5;
    int i0 = blockIdx.x * SCAN_PER + t * 4;
    int4 c = *(const int4*)&g_cnt[i0];
    int v0 = c.x, v1 = c.y, v2 = c.z, v3 = c.w;
    int s = v0 + v1 + v2 + v3;
    // warp inclusive scan of s
    int ps = s;
    #pragma unroll
    for (int off = 1; off < 32; off <<= 1) {
        int u = __shfl_up_sync(0xffffffffu, ps, off);
        if (lane >= off) ps += u;
    }
    if (lane == 31) wsum[wid] = ps;
    __syncthreads();
    if (t == 0) {
        int run = 0;
        #pragma unroll
        for (int w = 0; w < 8; w++) { int u = wsum[w]; wsum[w] = run; run += u; }
    }
    __syncthreads();
    int run = g_bsum[blockIdx.x] + wsum[wid] + (ps - s);
    if (i0 + 0 < n) { g_off[i0 + 0] = run; g_fill[i0 + 0] = run; } run += v0;
    if (i0 + 1 < n) { g_off[i0 + 1] = run; g_fill[i0 + 1] = run; } run += v1;
    if (i0 + 2 < n) { g_off[i0 + 2] = run; g_fill[i0 + 2] = run; } run += v2;
    if (i0 + 3 < n) { g_off[i0 + 3] = run; g_fill[i0 + 3] = run; } run += v3;
    if (i0 <= n - 1 && n - 1 < i0 + 4) {
        // this thread owns element n-1: write total edge count to g_off[n]
        int excl = g_bsum[blockIdx.x] + wsum[wid] + (ps - s);
        int vv[4] = {v0, v1, v2, v3};
        for (int j = 0; j < 4; j++) {
            if (i0 + j == n - 1) { g_off[n] = excl + vv[j]; }
            excl += vv[j];
        }
    }
}

__global__ void dinv_kernel(int n) {
    int i = blockIdx.x * blockDim.x + threadIdx.x;
    if (i < n) g_dinv[i] = rsqrtf((float)(g_cnt[i] + 1));   // +1 self-loop
}

// Fill CSR: g_src grouped by dst
__global__ void fill_kernel(int E) {
    int e = blockIdx.x * blockDim.x + threadIdx.x;
    if (e >= E) return;
    int2 ed = g_edges[e];
    int pos = atomicAdd(&g_fill[ed.y], 1);
    g_src[pos] = ed.x;
}

// ---------------------------------------------------------------------------
// Atomic-free aggregation: B[d,:] = A[d,:] + sum_{s in CSR[d]} A[s,:]
// One warp per node; lane owns a float2 (32*8B = 256B row).
__global__ void aggregate_kernel(const float* __restrict__ A, float* __restrict__ B, int n) {
    int warp = (blockIdx.x * blockDim.x + threadIdx.x) >> 5;
    int lane = threadIdx.x & 31;
    if (warp >= n) return;
    int beg = g_off[warp];
    int end = g_off[warp + 1];
    const float2* Ab = (const float2*)A;
    float2 acc = Ab[(size_t)warp * 32 + lane];   // self-loop term
    int i = beg;
    for (; i + 4 <= end; i += 4) {
        int s0 = g_src[i], s1 = g_src[i + 1], s2 = g_src[i + 2], s3 = g_src[i + 3];
        float2 v0 = Ab[(size_t)s0 * 32 + lane];
        float2 v1 = Ab[(size_t)s1 * 32 + lane];
        float2 v2 = Ab[(size_t)s2 * 32 + lane];
        float2 v3 = Ab[(size_t)s3 * 32 + lane];
        acc.x += (v0.x + v1.x) + (v2.x + v3.x);
        acc.y += (v0.y + v1.y) + (v2.y + v3.y);
    }
    for (; i < end; i++) {
        int s = g_src[i];
        float2 v = Ab[(size_t)s * 32 + lane];
        acc.x += v.x;
        acc.y += v.y;
    }
    ((float2*)B)[(size_t)warp * 32 + lane] = acc;
}

// ---------------------------------------------------------------------------
// Tiled fp32 GEMM: out = f(X) @ W, 64-row tiles, 4x4 thread tile.
// TRANS: x_load = relu(dinv[row]*x + bin[col])
// FC==0: epilogue v *= dinv[row], write O1 (gather source A)
// FC==1: epilogue v += bout[col], write O1
template<int K, int N, bool TRANS, bool FC>
__global__ void gemm_kernel(const float* X, const float* __restrict__ W,
                            const float* __restrict__ bin, const float* __restrict__ bout,
                            float* __restrict__ O1, int n) {
    constexpr int TX = N / 4;
    constexpr int NT = TX * 16;
    __shared__ float Xs[64][65];
    __shared__ float Ws[64][N];
    int row0 = blockIdx.x * 64;
    int tx = threadIdx.x, ty = threadIdx.y;
    int tid = ty * TX + tx;
    float acc[4][4] = {};

    for (int k0 = 0; k0 < K; k0 += 64) {
        for (int i = tid; i < 64 * 16; i += NT) {
            int r = i >> 4, c4 = i & 15;
            float4 v = make_float4(0.f, 0.f, 0.f, 0.f);
            int row = row0 + r;
            if (row < n) {
                v = *(const float4*)(X + (size_t)row * K + k0 + c4 * 4);
                if (TRANS) {
                    float s = g_dinv[row];
                    v.x = fmaxf(fmaf(v.x, s, bin[k0 + c4*4 + 0]), 0.f);
                    v.y = fmaxf(fmaf(v.y, s, bin[k0 + c4*4 + 1]), 0.f);
                    v.z = fmaxf(fmaf(v.z, s, bin[k0 + c4*4 + 2]), 0.f);
                    v.w = fmaxf(fmaf(v.w, s, bin[k0 + c4*4 + 3]), 0.f);
                }
            }
            Xs[r][c4 * 4 + 0] = v.x; Xs[r][c4 * 4 + 1] = v.y;
            Xs[r][c4 * 4 + 2] = v.z; Xs[r][c4 * 4 + 3] = v.w;
        }
        for (int i = tid; i < 64 * (N / 4); i += NT) {
            int r = i / (N / 4), c4 = i % (N / 4);
            float4 v = *(const float4*)(W + (size_t)(k0 + r) * N + c4 * 4);
            *(float4*)&Ws[r][c4 * 4] = v;
        }
        __syncthreads();
        #pragma unroll
        for (int k = 0; k < 64; k++) {
            float4 w = *(float4*)&Ws[k][tx * 4];
            #pragma unroll
            for (int i = 0; i < 4; i++) {
                float a = Xs[ty * 4 + i][k];
                acc[i][0] += a * w.x;
                acc[i][1] += a * w.y;
                acc[i][2] += a * w.z;
                acc[i][3] += a * w.w;
            }
        }
        __syncthreads();
    }

    #pragma unroll
    for (int i = 0; i < 4; i++) {
        int row = row0 + ty * 4 + i;
        if (row >= n) continue;
        float4 o;
        if (FC) {
            o.x = acc[i][0] + bout[tx*4 + 0];
            o.y = acc[i][1] + bout[tx*4 + 1];
            o.z = acc[i][2] + bout[tx*4 + 2];
            o.w = acc[i][3] + bout[tx*4 + 3];
        } else {
            float s = g_dinv[row];
            o.x = acc[i][0] * s;
            o.y = acc[i][1] * s;
            o.z = acc[i][2] * s;
            o.w = acc[i][3] * s;
        }
        *(float4*)(O1 + (size_t)row * N + tx * 4) = o;
    }
}

// ---------------------------------------------------------------------------
extern "C" void kernel_launch(void* const* d_in, const int* in_sizes, int n_in,
                              void* d_out, int out_size) {
    const float* x   = (const float*)d_in[0];
    const void*  ei  = d_in[1];
    const float* W1  = (const float*)d_in[3];
    const float* b1  = (const float*)d_in[4];
    const float* W2  = (const float*)d_in[5];
    const float* b2  = (const float*)d_in[6];
    const float* Wfc = (const float*)d_in[7];
    const float* bfc = (const float*)d_in[8];
    float* out = (float*)d_out;

    int n = in_sizes[0] / 128;   // 100000
    int E = in_sizes[1] / 2;     // 1600000

    float *A, *B;
    cudaGetSymbolAddress((void**)&A, g_A);
    cudaGetSymbolAddress((void**)&B, g_B);

    int nb_n  = (n + 255) / 256;
    int nb_E  = (E + 255) / 256;
    int nb_ag = (n * 32 + 255) / 256;            // warp per node
    int nb_g  = (n + 63) / 64;
    int nb_sc = (n + SCAN_PER - 1) / SCAN_PER;   // scan blocks (98)

    // Prep: dtype probe, counts, 3-phase scan -> CSR offsets, dinv, CSR fill
    probe_dtype<<<1, 256>>>((const long long*)ei);
    init_cnt<<<(CNT_PAD + 255) / 256, 256>>>();
    convert_cnt<<<nb_E, 256>>>(ei, E);
    scan_sums<<<nb_sc, 256>>>(n);
    scan_tops<<<1, 128>>>(nb_sc);
    scan_write<<<nb_sc, 256>>>(n);
    dinv_kernel<<<nb_n, 256>>>(n);
    fill_kernel<<<nb_E, 256>>>(E);

    // Layer 1: A = dinv*(x@W1); B = aggregate(A)
    gemm_kernel<128, 64, false, false><<<nb_g, dim3(16, 16)>>>(x, W1, nullptr, nullptr, A, n);
    aggregate_kernel<<<nb_ag, 256>>>(A, B, n);

    // Layer 2: X2 = relu(dinv*B + b1) on load; A = dinv*(X2@W2); B = aggregate(A)
    gemm_kernel<64, 64, true, false><<<nb_g, dim3(16, 16)>>>(B, W2, b1, nullptr, A, n);
    aggregate_kernel<<<nb_ag, 256>>>(A, B, n);

    // FC: out = relu(dinv*B + b2) @ Wfc + bfc
    gemm_kernel<64, 32, true, true><<<nb_g, dim3(8, 16)>>>(B, Wfc, b2, bfc, out, n);
}

// round 16
// speedup vs baseline: 1.7356x; 1.0109x over previous
#include <cuda_runtime.h>
#include <cuda_bf16.h>
#include <math.h>

#define NMAX   100000
#define EMAX   1600000
#define FH     64
#define SCAN_PER 1024                       // elems per scan block
#define SCAN_NB  ((NMAX + SCAN_PER - 1) / SCAN_PER)
#define CNT_PAD  (SCAN_NB * SCAN_PER)       // padded count-array size (int4-safe)

// Scratch (alloc-free rule: __device__ globals)
__device__ float g_A[NMAX * FH];      // gather source h'
__device__ float g_B[NMAX * FH];      // aggregation output
__device__ float g_dinv[NMAX];
__device__ int2  g_edges[EMAX];       // packed (src,dst)
__device__ int   g_cnt[CNT_PAD];      // in-degree (excl self-loop), padded
__device__ int   g_off[NMAX + 1];     // CSR offsets
__device__ int   g_fill[NMAX];        // fill cursors
__device__ int   g_src[EMAX];         // CSR src indices (grouped by dst)
__device__ int   g_bsum[256];         // scan block sums
__device__ int   g_is64;

// f32x2 packed-FMA helpers (FFMA2 only reachable via PTX)
#define PACK2(d, x, y) asm("mov.b64 %0,{%1,%2};" : "=l"(d) : "f"(x), "f"(y))
#define DUP2(d, x)     asm("mov.b64 %0,{%1,%1};" : "=l"(d) : "f"(x))
#define FMA2(c, a, b)  asm("fma.rn.f32x2 %0,%1,%2,%0;" : "+l"(c) : "l"(a), "l"(b))
#define UNPK(lo, hi, s) asm("mov.b64 {%0,%1},%2;" : "=f"(lo), "=f"(hi) : "l"(s))

// ---------------------------------------------------------------------------
// Fused: zero counts (grid-wide) + dtype probe (block 0).
// int64 detection: edge values < 100000, so all high words of the first 1024
// 8-byte slots are 0 iff dtype is int64.
__global__ void init_probe(const long long* __restrict__ ei) {
    int i = blockIdx.x * blockDim.x + threadIdx.x;
    if (i < CNT_PAD) g_cnt[i] = 0;
    if (blockIdx.x == 0) {
        __shared__ int any;
        if (threadIdx.x == 0) any = 0;
        __syncthreads();
        for (int j = threadIdx.x; j < 1024; j += blockDim.x) {
            long long v = ei[j];
            if ((v >> 32) != 0) any = 1;
        }
        __syncthreads();
        if (threadIdx.x == 0) g_is64 = (any == 0) ? 1 : 0;
    }
}

// Convert edges to packed int2 + count in-degree
__global__ void convert_cnt(const void* __restrict__ ei, int E) {
    int e = blockIdx.x * blockDim.x + threadIdx.x;
    if (e >= E) return;
    int s, d;
    if (g_is64) {
        const long long* p = (const long long*)ei;
        s = (int)p[e]; d = (int)p[E + e];
    } else {
        const int* p = (const int*)ei;
        s = p[e]; d = p[E + e];
    }
    g_edges[e] = make_int2(s, d);
    atomicAdd(&g_cnt[d], 1);
}

// ---------------------------------------------------------------------------
// Multi-block exclusive scan of g_cnt[0..n) -> g_off (+ g_fill, g_off[n], dinv)
// Phase 1: per-block sums (256 threads x 4 elems, int4 loads)
__global__ void scan_sums(int n) {
    __shared__ int red[256];
    int t = threadIdx.x;
    int i0 = blockIdx.x * SCAN_PER + t * 4;
    int4 v = *(const int4*)&g_cnt[i0];      // padded; counts beyond n are 0
    int s = v.x + v.y + v.z + v.w;
    red[t] = s;
    __syncthreads();
    #pragma unroll
    for (int off = 128; off > 0; off >>= 1) {
        if (t < off) red[t] += red[t + off];
        __syncthreads();
    }
    if (t == 0) g_bsum[blockIdx.x] = red[0];
}

// Phase 2: single block exclusive scan of block sums (nb <= 128)
__global__ void scan_tops(int nb) {
    __shared__ int sh[128];
    int t = threadIdx.x;
    int orig = (t < nb) ? g_bsum[t] : 0;
    sh[t] = orig;
    __syncthreads();
    #pragma unroll
    for (int off = 1; off < 128; off <<= 1) {
        int u = (t >= off) ? sh[t - off] : 0;
        __syncthreads();
        sh[t] += u;
        __syncthreads();
    }
    if (t < nb) g_bsum[t] = sh[t] - orig;   // exclusive
}

// Phase 3: local scan + write offsets/fill + fused dinv = rsqrt(cnt+1)
__global__ void scan_write(int n) {
    __shared__ int wsum[8];
    int t = threadIdx.x;
    int lane = t & 31, wid = t >> 5;
    int i0 = blockIdx.x * SCAN_PER + t * 4;
    int4 c = *(const int4*)&g_cnt[i0];
    int v0 = c.x, v1 = c.y, v2 = c.z, v3 = c.w;
    int s = v0 + v1 + v2 + v3;
    // warp inclusive scan of s
    int ps = s;
    #pragma unroll
    for (int off = 1; off < 32; off <<= 1) {
        int u = __shfl_up_sync(0xffffffffu, ps, off);
        if (lane >= off) ps += u;
    }
    if (lane == 31) wsum[wid] = ps;
    __syncthreads();
    if (t == 0) {
        int run = 0;
        #pragma unroll
        for (int w = 0; w < 8; w++) { int u = wsum[w]; wsum[w] = run; run += u; }
    }
    __syncthreads();
    int run = g_bsum[blockIdx.x] + wsum[wid] + (ps - s);
    if (i0 + 0 < n) { g_off[i0+0] = run; g_fill[i0+0] = run; g_dinv[i0+0] = rsqrtf((float)(v0+1)); } run += v0;
    if (i0 + 1 < n) { g_off[i0+1] = run; g_fill[i0+1] = run; g_dinv[i0+1] = rsqrtf((float)(v1+1)); } run += v1;
    if (i0 + 2 < n) { g_off[i0+2] = run; g_fill[i0+2] = run; g_dinv[i0+2] = rsqrtf((float)(v2+1)); } run += v2;
    if (i0 + 3 < n) { g_off[i0+3] = run; g_fill[i0+3] = run; g_dinv[i0+3] = rsqrtf((float)(v3+1)); } run += v3;
    if (i0 <= n - 1 && n - 1 < i0 + 4) {
        // this thread owns element n-1: write total edge count to g_off[n]
        int excl = g_bsum[blockIdx.x] + wsum[wid] + (ps - s);
        int vv[4] = {v0, v1, v2, v3};
        for (int j = 0; j < 4; j++) {
            if (i0 + j == n - 1) { g_off[n] = excl + vv[j]; }
            excl += vv[j];
        }
    }
}

// Fill CSR: g_src grouped by dst
__global__ void fill_kernel(int E) {
    int e = blockIdx.x * blockDim.x + threadIdx.x;
    if (e >= E) return;
    int2 ed = g_edges[e];
    int pos = atomicAdd(&g_fill[ed.y], 1);
    g_src[pos] = ed.x;
}

// ---------------------------------------------------------------------------
// Atomic-free aggregation: B[d,:] = A[d,:] + sum_{s in CSR[d]} A[s,:]
// One warp per node; lane owns a float2 (32*8B = 256B row).
__global__ void aggregate_kernel(const float* __restrict__ A, float* __restrict__ B, int n) {
    int warp = (blockIdx.x * blockDim.x + threadIdx.x) >> 5;
    int lane = threadIdx.x & 31;
    if (warp >= n) return;
    int beg = g_off[warp];
    int end = g_off[warp + 1];
    const float2* Ab = (const float2*)A;
    float2 acc = Ab[(size_t)warp * 32 + lane];   // self-loop term
    int i = beg;
    for (; i + 4 <= end; i += 4) {
        int s0 = g_src[i], s1 = g_src[i + 1], s2 = g_src[i + 2], s3 = g_src[i + 3];
        float2 v0 = Ab[(size_t)s0 * 32 + lane];
        float2 v1 = Ab[(size_t)s1 * 32 + lane];
        float2 v2 = Ab[(size_t)s2 * 32 + lane];
        float2 v3 = Ab[(size_t)s3 * 32 + lane];
        acc.x += (v0.x + v1.x) + (v2.x + v3.x);
        acc.y += (v0.y + v1.y) + (v2.y + v3.y);
    }
    for (; i < end; i++) {
        int s = g_src[i];
        float2 v = Ab[(size_t)s * 32 + lane];
        acc.x += v.x;
        acc.y += v.y;
    }
    ((float2*)B)[(size_t)warp * 32 + lane] = acc;
}

// ---------------------------------------------------------------------------
// Tiled GEMM, FFMA2 inner product: out = f(X) @ W, 64-row tiles, 4x4 tile.
// Structure identical to the proven R1 GEMM; only the accumulate uses
// fma.rn.f32x2 with column-paired u64 accumulators (same 16 regs).
// TRANS: x_load = relu(dinv[row]*x + bin[col])
// FC==0: epilogue v *= dinv[row], write O1 (gather source A)
// FC==1: epilogue v += bout[col], write O1
template<int K, int N, bool TRANS, bool FC>
__global__ void gemm_kernel(const float* X, const float* __restrict__ W,
                            const float* __restrict__ bin, const float* __restrict__ bout,
                            float* __restrict__ O1, int n) {
    constexpr int TX = N / 4;
    constexpr int NT = TX * 16;
    __shared__ float Xs[64][65];
    __shared__ float Ws[64][N];
    int row0 = blockIdx.x * 64;
    int tx = threadIdx.x, ty = threadIdx.y;
    int tid = ty * TX + tx;
    unsigned long long acc2[4][2];
    #pragma unroll
    for (int i = 0; i < 4; i++) { acc2[i][0] = 0ull; acc2[i][1] = 0ull; }

    for (int k0 = 0; k0 < K; k0 += 64) {
        for (int i = tid; i < 64 * 16; i += NT) {
            int r = i >> 4, c4 = i & 15;
            float4 v = make_float4(0.f, 0.f, 0.f, 0.f);
            int row = row0 + r;
            if (row < n) {
                v = *(const float4*)(X + (size_t)row * K + k0 + c4 * 4);
                if (TRANS) {
                    float s = g_dinv[row];
                    v.x = fmaxf(fmaf(v.x, s, bin[k0 + c4*4 + 0]), 0.f);
                    v.y = fmaxf(fmaf(v.y, s, bin[k0 + c4*4 + 1]), 0.f);
                    v.z = fmaxf(fmaf(v.z, s, bin[k0 + c4*4 + 2]), 0.f);
                    v.w = fmaxf(fmaf(v.w, s, bin[k0 + c4*4 + 3]), 0.f);
                }
            }
            Xs[r][c4 * 4 + 0] = v.x; Xs[r][c4 * 4 + 1] = v.y;
            Xs[r][c4 * 4 + 2] = v.z; Xs[r][c4 * 4 + 3] = v.w;
        }
        for (int i = tid; i < 64 * (N / 4); i += NT) {
            int r = i / (N / 4), c4 = i % (N / 4);
            float4 v = *(const float4*)(W + (size_t)(k0 + r) * N + c4 * 4);
            *(float4*)&Ws[r][c4 * 4] = v;
        }
        __syncthreads();
        #pragma unroll
        for (int k = 0; k < 64; k++) {
            float4 w = *(float4*)&Ws[k][tx * 4];
            unsigned long long w01, w23;
            PACK2(w01, w.x, w.y);
            PACK2(w23, w.z, w.w);
            #pragma unroll
            for (int i = 0; i < 4; i++) {
                float a = Xs[ty * 4 + i][k];
                unsigned long long ad;
                DUP2(ad, a);
                FMA2(acc2[i][0], ad, w01);
                FMA2(acc2[i][1], ad, w23);
            }
        }
        __syncthreads();
    }

    #pragma unroll
    for (int i = 0; i < 4; i++) {
        int row = row0 + ty * 4 + i;
        if (row >= n) continue;
        float4 o;
        UNPK(o.x, o.y, acc2[i][0]);
        UNPK(o.z, o.w, acc2[i][1]);
        if (FC) {
            o.x += bout[tx*4 + 0];
            o.y += bout[tx*4 + 1];
            o.z += bout[tx*4 + 2];
            o.w += bout[tx*4 + 3];
        } else {
            float s = g_dinv[row];
            o.x *= s; o.y *= s; o.z *= s; o.w *= s;
        }
        *(float4*)(O1 + (size_t)row * N + tx * 4) = o;
    }
}

// ---------------------------------------------------------------------------
extern "C" void kernel_launch(void* const* d_in, const int* in_sizes, int n_in,
                              void* d_out, int out_size) {
    const float* x   = (const float*)d_in[0];
    const void*  ei  = d_in[1];
    const float* W1  = (const float*)d_in[3];
    const float* b1  = (const float*)d_in[4];
    const float* W2  = (const float*)d_in[5];
    const float* b2  = (const float*)d_in[6];
    const float* Wfc = (const float*)d_in[7];
    const float* bfc = (const float*)d_in[8];
    float* out = (float*)d_out;

    int n = in_sizes[0] / 128;   // 100000
    int E = in_sizes[1] / 2;     // 1600000

    float *A, *B;
    cudaGetSymbolAddress((void**)&A, g_A);
    cudaGetSymbolAddress((void**)&B, g_B);

    int nb_E  = (E + 255) / 256;
    int nb_ag = (n * 32 + 255) / 256;            // warp per node
    int nb_g  = (n + 63) / 64;
    int nb_sc = (n + SCAN_PER - 1) / SCAN_PER;   // scan blocks (98)

    // Prep: fused init+probe, counts, 3-phase scan (offsets+fill+dinv), fill
    init_probe<<<(CNT_PAD + 255) / 256, 256>>>((const long long*)ei);
    convert_cnt<<<nb_E, 256>>>(ei, E);
    scan_sums<<<nb_sc, 256>>>(n);
    scan_tops<<<1, 128>>>(nb_sc);
    scan_write<<<nb_sc, 256>>>(n);
    fill_kernel<<<nb_E, 256>>>(E);

    // Layer 1: A = dinv*(x@W1); B = aggregate(A)
    gemm_kernel<128, 64, false, false><<<nb_g, dim3(16, 16)>>>(x, W1, nullptr, nullptr, A, n);
    aggregate_kernel<<<nb_ag, 256>>>(A, B, n);

    // Layer 2: X2 = relu(dinv*B + b1) on load; A = dinv*(X2@W2); B = aggregate(A)
    gemm_kernel<64, 64, true, false><<<nb_g, dim3(16, 16)>>>(B, W2, b1, nullptr, A, n);
    aggregate_kernel<<<nb_ag, 256>>>(A, B, n);

    // FC: out = relu(dinv*B + b2) @ Wfc + bfc
    gemm_kernel<64, 32, true, true><<<nb_g, dim3(8, 16)>>>(B, Wfc, b2, bfc, out, n);
}